// round 1
// baseline (speedup 1.0000x reference)
#include <cuda_runtime.h>
#include <cuda_bf16.h>
#include <math.h>

// Problem constants
#define B_    32
#define N_    4096
#define F_    768
#define K_    8
#define D_    256
#define NB_   (B_ * N_)          // 131072 rows
#define NCHUNK 16                // n split into 16 chunks of 256
#define SCALE_ 0.0625f           // 256^-0.5
#define EPS_   1e-8f

// ---------------- scratch (device globals; no allocation allowed) ----------
__device__ float g_kmat[(size_t)NB_ * D_];      // (B,N,256) k
__device__ float g_vmat[(size_t)NB_ * D_];      // (B,N,256) v
__device__ float g_mean[NB_];
__device__ float g_rstd[NB_];
__device__ float g_attn[(size_t)B_ * K_ * N_];  // iteration attn
__device__ float g_q[B_ * K_ * D_];
__device__ float g_slots[B_ * K_ * D_];
__device__ float g_partial[B_ * K_ * NCHUNK];
__device__ float g_rowsum[B_ * K_];
__device__ float g_updpart[(size_t)B_ * NCHUNK * K_ * D_];
__device__ float g_WihT[768 * 256];
__device__ float g_WhhT[768 * 256];
__device__ float g_W1T[256 * 256];
__device__ float g_W2T[256 * 256];
__device__ float g_WqT[256 * 256];

// ---------------- LN row stats over features ------------------------------
__global__ void __launch_bounds__(256) ln_stats(const float* __restrict__ feat) {
    int row = blockIdx.x;
    const float* p = feat + (size_t)row * F_;
    int t = threadIdx.x;
    float x0 = p[t], x1 = p[t + 256], x2 = p[t + 512];
    float s  = x0 + x1 + x2;
    float ss = x0 * x0 + x1 * x1 + x2 * x2;
    __shared__ float r1[256], r2[256];
    r1[t] = s; r2[t] = ss;
    __syncthreads();
    for (int o = 128; o; o >>= 1) {
        if (t < o) { r1[t] += r1[t + o]; r2[t] += r2[t + o]; }
        __syncthreads();
    }
    if (t == 0) {
        float mean = r1[0] * (1.f / 768.f);
        float var  = r2[0] * (1.f / 768.f) - mean * mean;
        g_mean[row] = mean;
        g_rstd[row] = rsqrtf(var + 1e-5f);
    }
}

// ---------------- generic transpose into device-global targets ------------
__device__ __forceinline__ float* tgt_ptr(int sel) {
    switch (sel) {
        case 0: return g_WihT;
        case 1: return g_WhhT;
        case 2: return g_W1T;
        case 3: return g_W2T;
        default: return g_WqT;
    }
}

__global__ void transpose_k(const float* __restrict__ src, int R, int C, int sel) {
    __shared__ float tile[32][33];
    float* dst = tgt_ptr(sel);
    int bx = blockIdx.x * 32, by = blockIdx.y * 32;
    int x = bx + threadIdx.x;
    for (int i = 0; i < 32; i += 8) {
        int y = by + threadIdx.y + i;
        if (y < R && x < C) tile[threadIdx.y + i][threadIdx.x] = src[(size_t)y * C + x];
    }
    __syncthreads();
    int x2 = by + threadIdx.x;
    for (int i = 0; i < 32; i += 8) {
        int y2 = bx + threadIdx.y + i;
        if (y2 < C && x2 < R) dst[(size_t)y2 * R + x2] = tile[threadIdx.x][threadIdx.y + i];
    }
}

// ---------------- fused LN + K/V projection GEMM --------------------------
// C[131072, 512] = LN(features)[131072,768] @ [Wk;Wv]^T
// BM=128, BN=64, BK=16, 256 threads, thread tile 8x4.
__global__ void __launch_bounds__(256) kv_gemm(const float* __restrict__ feat,
                                               const float* __restrict__ gin,
                                               const float* __restrict__ bin,
                                               const float* __restrict__ Wk,
                                               const float* __restrict__ Wv) {
    __shared__ float As[16][128];
    __shared__ float Bs[16][64];
    int jb = blockIdx.x;           // 0..7 : which 64-col block of the 512 outputs
    int ib = blockIdx.y;           // 0..1023
    const float* __restrict__ W = (jb < 4) ? Wk : Wv;
    float* __restrict__ dst = (jb < 4) ? g_kmat : g_vmat;
    int hbase = (jb & 3) * 64;

    int t  = threadIdx.x;
    int tm = t & 15, tn = t >> 4;  // 16 x 16 thread grid
    int lr = t >> 2, cg = t & 3;   // loader mapping: 64 rows x 4 col-groups
    int rowbase = ib * 128;

    float m0 = g_mean[rowbase + lr],      r0 = g_rstd[rowbase + lr];
    float m1 = g_mean[rowbase + lr + 64], r1 = g_rstd[rowbase + lr + 64];

    const float* fp0 = feat + (size_t)(rowbase + lr) * F_ + cg * 4;
    const float* fp1 = feat + (size_t)(rowbase + lr + 64) * F_ + cg * 4;
    const float* wp  = W + (size_t)(hbase + lr) * F_ + cg * 4;

    float acc[8][4];
#pragma unroll
    for (int i = 0; i < 8; i++)
#pragma unroll
        for (int j = 0; j < 4; j++) acc[i][j] = 0.f;

    for (int k0 = 0; k0 < F_; k0 += 16) {
        float4 gi = *(const float4*)(gin + k0 + cg * 4);
        float4 bi = *(const float4*)(bin + k0 + cg * 4);
        float4 x0 = *(const float4*)(fp0 + k0);
        float4 x1 = *(const float4*)(fp1 + k0);
        float4 w  = *(const float4*)(wp + k0);
        int kc = cg * 4;
        As[kc + 0][lr]      = (x0.x - m0) * r0 * gi.x + bi.x;
        As[kc + 1][lr]      = (x0.y - m0) * r0 * gi.y + bi.y;
        As[kc + 2][lr]      = (x0.z - m0) * r0 * gi.z + bi.z;
        As[kc + 3][lr]      = (x0.w - m0) * r0 * gi.w + bi.w;
        As[kc + 0][lr + 64] = (x1.x - m1) * r1 * gi.x + bi.x;
        As[kc + 1][lr + 64] = (x1.y - m1) * r1 * gi.y + bi.y;
        As[kc + 2][lr + 64] = (x1.z - m1) * r1 * gi.z + bi.z;
        As[kc + 3][lr + 64] = (x1.w - m1) * r1 * gi.w + bi.w;
        Bs[kc + 0][lr] = w.x;
        Bs[kc + 1][lr] = w.y;
        Bs[kc + 2][lr] = w.z;
        Bs[kc + 3][lr] = w.w;
        __syncthreads();
#pragma unroll
        for (int kk = 0; kk < 16; kk++) {
            float4 a0 = *(const float4*)&As[kk][tm * 8];
            float4 a1 = *(const float4*)&As[kk][tm * 8 + 4];
            float4 b4 = *(const float4*)&Bs[kk][tn * 4];
            float av[8] = {a0.x, a0.y, a0.z, a0.w, a1.x, a1.y, a1.z, a1.w};
            float bv[4] = {b4.x, b4.y, b4.z, b4.w};
#pragma unroll
            for (int i = 0; i < 8; i++)
#pragma unroll
                for (int j = 0; j < 4; j++) acc[i][j] += av[i] * bv[j];
        }
        __syncthreads();
    }
#pragma unroll
    for (int i = 0; i < 8; i++) {
        int grow = rowbase + tm * 8 + i;
        float4 o = make_float4(acc[i][0], acc[i][1], acc[i][2], acc[i][3]);
        *(float4*)(dst + (size_t)grow * D_ + hbase + tn * 4) = o;
    }
}

// ---------------- slot init ------------------------------------------------
__global__ void __launch_bounds__(256) copy_slots(const float* __restrict__ prev) {
    int i = blockIdx.x * 256 + threadIdx.x;
    g_slots[i] = prev[i];
}

// ---------------- q projection (LN slots + Wq) -----------------------------
__global__ void __launch_bounds__(256) q_proj(const float* __restrict__ g_sw,
                                              const float* __restrict__ b_sw) {
    int idx = blockIdx.x;  // b*8+k
    int t = threadIdx.x;
    __shared__ float r1[256], r2[256], lnv[256];
    float x = g_slots[idx * D_ + t];
    r1[t] = x; r2[t] = x * x;
    __syncthreads();
    for (int o = 128; o; o >>= 1) {
        if (t < o) { r1[t] += r1[t + o]; r2[t] += r2[t + o]; }
        __syncthreads();
    }
    float mean = r1[0] * (1.f / 256.f);
    float var  = r2[0] * (1.f / 256.f) - mean * mean;
    float rstd = rsqrtf(var + 1e-5f);
    __syncthreads();  // protect r1/r2 reads before (unused later, but clean)
    lnv[t] = (x - mean) * rstd * g_sw[t] + b_sw[t];
    __syncthreads();
    float acc = 0.f;
#pragma unroll 8
    for (int d = 0; d < 256; d++) acc += lnv[d] * g_WqT[d * 256 + t];
    g_q[idx * D_ + t] = acc;
}

// ---------------- logits + softmax over K + partial row sums ---------------
// grid (B, 16), 256 threads = 8 warps; each warp owns tokens w + 8*it.
__global__ void __launch_bounds__(256) logits_softmax(float* __restrict__ attn_ext,
                                                      int to_ext) {
    int b = blockIdx.x, c = blockIdx.y;
    int t = threadIdx.x, w = t >> 5, lane = t & 31;
    float* attn_out = to_ext ? attn_ext : g_attn;

    __shared__ float4 qs4[K_ * 64];  // 8 slots x 256 floats
    __shared__ float wsum[8][K_];
    const float4* qg = (const float4*)(g_q + b * K_ * D_);
    for (int i = t; i < K_ * 64; i += 256) qs4[i] = qg[i];
    __syncthreads();

    float accS[K_];
#pragma unroll
    for (int s = 0; s < K_; s++) accS[s] = 0.f;

    int nbase = c * 256;
    for (int it = 0; it < 32; it++) {
        int n = nbase + w + it * 8;
        const float4* kp = (const float4*)(g_kmat + ((size_t)(b * N_ + n)) * D_);
        float4 k0 = kp[lane], k1 = kp[32 + lane];
        float dots[K_];
#pragma unroll
        for (int s = 0; s < K_; s++) {
            float4 qa = qs4[s * 64 + lane];
            float4 qb = qs4[s * 64 + 32 + lane];
            float p = k0.x * qa.x + k0.y * qa.y + k0.z * qa.z + k0.w * qa.w +
                      k1.x * qb.x + k1.y * qb.y + k1.z * qb.z + k1.w * qb.w;
#pragma unroll
            for (int off = 16; off; off >>= 1) p += __shfl_xor_sync(0xFFFFFFFFu, p, off);
            dots[s] = p * SCALE_;
        }
        float mx = dots[0];
#pragma unroll
        for (int s = 1; s < K_; s++) mx = fmaxf(mx, dots[s]);
        float e[K_], den = 0.f;
#pragma unroll
        for (int s = 0; s < K_; s++) { e[s] = expf(dots[s] - mx); den += e[s]; }
        float inv = 1.f / den;
#pragma unroll
        for (int s = 0; s < K_; s++) accS[s] += e[s] * inv;
        if (lane < K_)
            attn_out[((size_t)(b * K_ + lane)) * N_ + n] = e[lane] * inv;
    }
    if (lane < K_) wsum[w][lane] = accS[lane];
    __syncthreads();
    if (t < K_) {
        float sm = 0.f;
        for (int w2 = 0; w2 < 8; w2++) sm += wsum[w2][t];
        g_partial[(b * K_ + t) * NCHUNK + c] = sm;
    }
}

// ---------------- deterministic row-sum reduce -----------------------------
__global__ void __launch_bounds__(256) rowsum_reduce() {
    int t = threadIdx.x;  // 256 = B*K
    float s = 0.f;
#pragma unroll
    for (int c = 0; c < NCHUNK; c++) s += g_partial[t * NCHUNK + c];
    g_rowsum[t] = s;
}

// ---------------- updates = attn_n @ v (n-split partials) ------------------
__global__ void __launch_bounds__(256) upd_partial() {
    int b = blockIdx.x, c = blockIdx.y;
    int t = threadIdx.x;
    __shared__ float an[K_][256];
#pragma unroll
    for (int s = 0; s < K_; s++) {
        float inv = 1.f / (g_rowsum[b * K_ + s] + EPS_);
        an[s][t] = g_attn[((size_t)(b * K_ + s)) * N_ + c * 256 + t] * inv;
    }
    __syncthreads();
    float acc[K_];
#pragma unroll
    for (int s = 0; s < K_; s++) acc[s] = 0.f;
    const float* vp = g_vmat + ((size_t)(b * N_ + c * 256)) * D_ + t;
#pragma unroll 4
    for (int nn = 0; nn < 256; nn++) {
        float v = vp[(size_t)nn * D_];
#pragma unroll
        for (int s = 0; s < K_; s++) acc[s] += an[s][nn] * v;
    }
    float* up = g_updpart + ((size_t)((b * NCHUNK + c) * K_)) * D_ + t;
#pragma unroll
    for (int s = 0; s < K_; s++) up[s * D_] = acc[s];
}

// ---------------- GRU cell + LN + MLP (per slot) ---------------------------
__global__ void __launch_bounds__(256) gru_mlp(const float* __restrict__ b_ih,
                                               const float* __restrict__ b_hh,
                                               const float* __restrict__ g_mw,
                                               const float* __restrict__ b_mw,
                                               const float* __restrict__ b1,
                                               const float* __restrict__ b2) {
    int idx = blockIdx.x;  // b*8+k
    int b = idx >> 3, k = idx & 7;
    int t = threadIdx.x;
    __shared__ float upd[256], slt[256], lnbuf[256], mbuf[256], r1[256], r2[256];

    float u = 0.f;
#pragma unroll
    for (int c = 0; c < NCHUNK; c++)
        u += g_updpart[((size_t)((b * NCHUNK + c) * K_ + k)) * D_ + t];
    upd[t] = u;
    float sv = g_slots[idx * D_ + t];
    slt[t] = sv;
    __syncthreads();

    float gir = b_ih[t], giz = b_ih[256 + t], gin = b_ih[512 + t];
    float ghr = b_hh[t], ghz = b_hh[256 + t], ghn = b_hh[512 + t];
#pragma unroll 4
    for (int d = 0; d < 256; d++) {
        float ud = upd[d], sd = slt[d];
        const float* wi = &g_WihT[d * 768];
        const float* wh = &g_WhhT[d * 768];
        gir += ud * wi[t];       ghr += sd * wh[t];
        giz += ud * wi[256 + t]; ghz += sd * wh[256 + t];
        gin += ud * wi[512 + t]; ghn += sd * wh[512 + t];
    }
    float r = 1.f / (1.f + expf(-(gir + ghr)));
    float z = 1.f / (1.f + expf(-(giz + ghz)));
    float nn = tanhf(gin + r * ghn);
    float h = (1.f - z) * nn + z * sv;

    r1[t] = h; r2[t] = h * h;
    __syncthreads();
    for (int o = 128; o; o >>= 1) {
        if (t < o) { r1[t] += r1[t + o]; r2[t] += r2[t + o]; }
        __syncthreads();
    }
    float mean = r1[0] * (1.f / 256.f);
    float var  = r2[0] * (1.f / 256.f) - mean * mean;
    float rstd = rsqrtf(var + 1e-5f);
    __syncthreads();
    lnbuf[t] = (h - mean) * rstd * g_mw[t] + b_mw[t];
    __syncthreads();

    float acc = b1[t];
#pragma unroll 8
    for (int d = 0; d < 256; d++) acc += lnbuf[d] * g_W1T[d * 256 + t];
    mbuf[t] = fmaxf(acc, 0.f);
    __syncthreads();

    float o = h + b2[t];
#pragma unroll 8
    for (int j = 0; j < 256; j++) o += mbuf[j] * g_W2T[j * 256 + t];
    g_slots[idx * D_ + t] = o;
}

// ---------------- final confidence blend -----------------------------------
__global__ void __launch_bounds__(256) blend(const float* __restrict__ prev,
                                             float* __restrict__ out_slots) {
    int idx = blockIdx.x;  // b*8+k
    int t = threadIdx.x;
    float mask = 1.f / (1.f + expf(-g_rowsum[idx] * (1.f / (float)N_)));
    out_slots[idx * D_ + t] =
        g_slots[idx * D_ + t] * mask + prev[idx * D_ + t] * (1.f - mask);
}

// ---------------- launch ----------------------------------------------------
extern "C" void kernel_launch(void* const* d_in, const int* in_sizes, int n_in,
                              void* d_out, int out_size) {
    const float* features = (const float*)d_in[0];
    const float* prev_slots = (const float*)d_in[1];
    const float* gin  = (const float*)d_in[2];
    const float* bin  = (const float*)d_in[3];
    const float* g_sw = (const float*)d_in[4];
    const float* b_sw = (const float*)d_in[5];
    const float* g_mw = (const float*)d_in[6];
    const float* b_mw = (const float*)d_in[7];
    const float* Wq   = (const float*)d_in[8];
    const float* Wk   = (const float*)d_in[9];
    const float* Wv   = (const float*)d_in[10];
    const float* W_ih = (const float*)d_in[11];
    const float* W_hh = (const float*)d_in[12];
    const float* b_ih = (const float*)d_in[13];
    const float* b_hh = (const float*)d_in[14];
    const float* W1   = (const float*)d_in[15];
    const float* b1   = (const float*)d_in[16];
    const float* W2   = (const float*)d_in[17];
    const float* b2   = (const float*)d_in[18];

    float* out = (float*)d_out;
    float* out_slots = out;                       // (B, K, 256)
    float* out_attn  = out + B_ * K_ * D_;        // (B, K, N)

    ln_stats<<<NB_, 256>>>(features);
    transpose_k<<<dim3(256 / 32, 768 / 32), dim3(32, 8)>>>(W_ih, 768, 256, 0);
    transpose_k<<<dim3(256 / 32, 768 / 32), dim3(32, 8)>>>(W_hh, 768, 256, 1);
    transpose_k<<<dim3(256 / 32, 256 / 32), dim3(32, 8)>>>(W1, 256, 256, 2);
    transpose_k<<<dim3(256 / 32, 256 / 32), dim3(32, 8)>>>(W2, 256, 256, 3);
    transpose_k<<<dim3(256 / 32, 256 / 32), dim3(32, 8)>>>(Wq, 256, 256, 4);

    kv_gemm<<<dim3(8, NB_ / 128), 256>>>(features, gin, bin, Wk, Wv);
    copy_slots<<<(B_ * K_ * D_) / 256, 256>>>(prev_slots);

    for (int it = 0; it < 3; it++) {
        q_proj<<<B_ * K_, 256>>>(g_sw, b_sw);
        logits_softmax<<<dim3(B_, NCHUNK), 256>>>(out_attn, 0);
        rowsum_reduce<<<1, 256>>>();
        upd_partial<<<dim3(B_, NCHUNK), 256>>>();
        gru_mlp<<<B_ * K_, 256>>>(b_ih, b_hh, g_mw, b_mw, b1, b2);
    }

    // final attention (written straight to output) + blend
    q_proj<<<B_ * K_, 256>>>(g_sw, b_sw);
    logits_softmax<<<dim3(B_, NCHUNK), 256>>>(out_attn, 1);
    rowsum_reduce<<<1, 256>>>();
    blend<<<B_ * K_, 256>>>(prev_slots, out_slots);
}

// round 4
// speedup vs baseline: 2.1040x; 2.1040x over previous
#include <cuda_runtime.h>
#include <cuda_bf16.h>
#include <math.h>
#include <stdint.h>

// Problem constants
#define B_    32
#define N_    4096
#define F_    768
#define K_    8
#define D_    256
#define NB_   (B_ * N_)          // 131072 rows
#define NCHUNK 16                // n split into 16 chunks of 256
#define SCALE_ 0.0625f           // 256^-0.5
#define EPS_   1e-8f

// ---------------- scratch (device globals; no allocation allowed) ----------
__device__ float g_kmat[(size_t)NB_ * D_];      // (B,N,256) k
__device__ float g_vmat[(size_t)NB_ * D_];      // (B,N,256) v
__device__ float g_mean[NB_];
__device__ float g_rstd[NB_];
__device__ float g_attn[(size_t)B_ * K_ * N_];  // iteration attn
__device__ float g_q[B_ * K_ * D_];
__device__ float g_slots[B_ * K_ * D_];
__device__ float g_partial[B_ * K_ * NCHUNK];
__device__ float g_rowsum[B_ * K_];
__device__ float g_updpart[(size_t)B_ * NCHUNK * K_ * D_];
__device__ float g_WihT[768 * 256];
__device__ float g_WhhT[768 * 256];
__device__ float g_W1T[256 * 256];
__device__ float g_W2T[256 * 256];
__device__ float g_WqT[256 * 256];

// =================== portable mma.sync helpers =============================
static __device__ __forceinline__ unsigned int smem_u32(const void* p) {
    unsigned int a;
    asm("{ .reg .u64 t; cvta.to.shared.u64 t, %1; cvt.u32.u64 %0, t; }"
        : "=r"(a) : "l"(p));
    return a;
}

#define LDSM4(R, addr)                                                         \
    asm volatile("ldmatrix.sync.aligned.m8n8.x4.shared.b16 {%0,%1,%2,%3}, [%4];" \
        : "=r"((R)[0]), "=r"((R)[1]), "=r"((R)[2]), "=r"((R)[3]) : "r"(addr))

#define MMA_BF16(D, A, B0, B1)                                                 \
    asm volatile("mma.sync.aligned.m16n8k16.row.col.f32.bf16.bf16.f32 "        \
        "{%0,%1,%2,%3},{%4,%5,%6,%7},{%8,%9},{%0,%1,%2,%3};"                   \
        : "+f"((D)[0]), "+f"((D)[1]), "+f"((D)[2]), "+f"((D)[3])               \
        : "r"((A)[0]), "r"((A)[1]), "r"((A)[2]), "r"((A)[3]), "r"(B0), "r"(B1))

#define STS128A(addr, a, b, c, d) \
    asm volatile("st.shared.v4.b32 [%0], {%1,%2,%3,%4};" :: "r"(addr), "r"(a), "r"(b), "r"(c), "r"(d) : "memory")

static __device__ __forceinline__ unsigned int pack_bf2(float lo, float hi) {
    __nv_bfloat162 h2 = __floats2bfloat162_rn(lo, hi);  // .x = lo half, .y = hi half
    return *(unsigned int*)&h2;
}

// SMEM layout for kv_mma (bytes): per stage Ahi/Alo/Bhi/Blo each 128 rows x 80B
#define ROWB   80      // 40 halfwords per row (32 data + 8 pad)
#define TILEB  10240   // 128 * 80
#define STAGEB (4 * TILEB)          // 40960
#define SMEM_MMA (2 * STAGEB)       // 81920

// ---------------- LN row stats over features ------------------------------
__global__ void __launch_bounds__(256) ln_stats(const float* __restrict__ feat) {
    int row = blockIdx.x;
    const float* p = feat + (size_t)row * F_;
    int t = threadIdx.x;
    float x0 = p[t], x1 = p[t + 256], x2 = p[t + 512];
    float s  = x0 + x1 + x2;
    float ss = x0 * x0 + x1 * x1 + x2 * x2;
    __shared__ float r1[256], r2[256];
    r1[t] = s; r2[t] = ss;
    __syncthreads();
    for (int o = 128; o; o >>= 1) {
        if (t < o) { r1[t] += r1[t + o]; r2[t] += r2[t + o]; }
        __syncthreads();
    }
    if (t == 0) {
        float mean = r1[0] * (1.f / 768.f);
        float var  = r2[0] * (1.f / 768.f) - mean * mean;
        g_mean[row] = mean;
        g_rstd[row] = rsqrtf(var + 1e-5f);
    }
}

// ---------------- generic transpose into device-global targets ------------
__device__ __forceinline__ float* tgt_ptr(int sel) {
    switch (sel) {
        case 0: return g_WihT;
        case 1: return g_WhhT;
        case 2: return g_W1T;
        case 3: return g_W2T;
        default: return g_WqT;
    }
}

__global__ void transpose_k(const float* __restrict__ src, int R, int C, int sel) {
    __shared__ float tile[32][33];
    float* dst = tgt_ptr(sel);
    int bx = blockIdx.x * 32, by = blockIdx.y * 32;
    int x = bx + threadIdx.x;
    for (int i = 0; i < 32; i += 8) {
        int y = by + threadIdx.y + i;
        if (y < R && x < C) tile[threadIdx.y + i][threadIdx.x] = src[(size_t)y * C + x];
    }
    __syncthreads();
    int x2 = by + threadIdx.x;
    for (int i = 0; i < 32; i += 8) {
        int y2 = bx + threadIdx.y + i;
        if (y2 < C && x2 < R) dst[(size_t)y2 * R + x2] = tile[threadIdx.x][threadIdx.y + i];
    }
}

// ---------------- bf16x3 HMMA fused LN + K/V projection --------------------
// C[131072, 512] = LN(features) @ [Wk;Wv]^T via mma.sync m16n8k16 bf16 with
// hi/lo operand splitting (3 MMAs per product term), fp32 accumulation.
// CTA tile 128x128, K chunks of 32, double-buffered SMEM.
__global__ void __launch_bounds__(256) kv_mma(const float* __restrict__ feat,
                                              const float* __restrict__ gin,
                                              const float* __restrict__ bin,
                                              const float* __restrict__ Wk,
                                              const float* __restrict__ Wv) {
    extern __shared__ char smem[];
    unsigned int sb = smem_u32(smem);
    int t = threadIdx.x, wid = t >> 5, lane = t & 31;
    int bx = blockIdx.x;                    // 0,1 -> Wk ; 2,3 -> Wv
    int rowbase = blockIdx.y * 128;
    const float* __restrict__ W = (bx < 2) ? Wk : Wv;
    float* __restrict__ dst = (bx < 2) ? g_kmat : g_vmat;
    int hbase = (bx & 1) * 128;             // output col base & W row base

    // loader role: thread t -> row t>>1, 16-float half (t&1)
    int lrow = t >> 1, lh = t & 1;
    float lm = g_mean[rowbase + lrow];
    float lrs = g_rstd[rowbase + lrow];
    const float* fptr = feat + (size_t)(rowbase + lrow) * F_ + lh * 16;
    const float* wptr = W + (size_t)(hbase + lrow) * F_ + lh * 16;
    unsigned int rowoff = (unsigned int)(lrow * ROWB + lh * 32);

    float4 ra[4], rb[4];
    auto fetch = [&](int c) {
        int k0 = c * 32;
#pragma unroll
        for (int j = 0; j < 4; j++) {
            ra[j] = *(const float4*)(fptr + k0 + j * 4);
            rb[j] = *(const float4*)(wptr + k0 + j * 4);
        }
    };
    auto stage = [&](int c, int s) {
        int k0 = c * 32;
        unsigned int stbase = sb + s * STAGEB;
        // ---- A tile with LN ----
        float y[16];
#pragma unroll
        for (int j = 0; j < 4; j++) {
            float4 g4 = *(const float4*)(gin + k0 + lh * 16 + j * 4);
            float4 b4 = *(const float4*)(bin + k0 + lh * 16 + j * 4);
            y[4 * j + 0] = (ra[j].x - lm) * lrs * g4.x + b4.x;
            y[4 * j + 1] = (ra[j].y - lm) * lrs * g4.y + b4.y;
            y[4 * j + 2] = (ra[j].z - lm) * lrs * g4.z + b4.z;
            y[4 * j + 3] = (ra[j].w - lm) * lrs * g4.w + b4.w;
        }
        unsigned int uh[8], ul[8];
#pragma unroll
        for (int j = 0; j < 8; j++) {
            unsigned int u = pack_bf2(y[2 * j], y[2 * j + 1]);
            float h0 = __uint_as_float(u << 16);
            float h1 = __uint_as_float(u & 0xFFFF0000u);
            uh[j] = u;
            ul[j] = pack_bf2(y[2 * j] - h0, y[2 * j + 1] - h1);
        }
        STS128A(stbase + rowoff,                 uh[0], uh[1], uh[2], uh[3]);
        STS128A(stbase + rowoff + 16,            uh[4], uh[5], uh[6], uh[7]);
        STS128A(stbase + TILEB + rowoff,         ul[0], ul[1], ul[2], ul[3]);
        STS128A(stbase + TILEB + rowoff + 16,    ul[4], ul[5], ul[6], ul[7]);
        // ---- B tile ----
        float z[16];
#pragma unroll
        for (int j = 0; j < 4; j++) {
            z[4 * j + 0] = rb[j].x; z[4 * j + 1] = rb[j].y;
            z[4 * j + 2] = rb[j].z; z[4 * j + 3] = rb[j].w;
        }
#pragma unroll
        for (int j = 0; j < 8; j++) {
            unsigned int u = pack_bf2(z[2 * j], z[2 * j + 1]);
            float h0 = __uint_as_float(u << 16);
            float h1 = __uint_as_float(u & 0xFFFF0000u);
            uh[j] = u;
            ul[j] = pack_bf2(z[2 * j] - h0, z[2 * j + 1] - h1);
        }
        STS128A(stbase + 2 * TILEB + rowoff,              uh[0], uh[1], uh[2], uh[3]);
        STS128A(stbase + 2 * TILEB + rowoff + 16,         uh[4], uh[5], uh[6], uh[7]);
        STS128A(stbase + 3 * TILEB + rowoff,              ul[0], ul[1], ul[2], ul[3]);
        STS128A(stbase + 3 * TILEB + rowoff + 16,         ul[4], ul[5], ul[6], ul[7]);
    };

    // warp tile: 32(m) x 64(n); warp grid 4(m) x 2(n)
    int wm = (wid & 3) * 32, wn = (wid >> 2) * 64;
    // per-lane ldmatrix base offsets (bytes, within a tile)
    unsigned int a_off = (unsigned int)((wm + (lane & 7) + ((lane >> 3) & 1) * 8) * ROWB + (lane >> 4) * 16);
    unsigned int b_off = (unsigned int)((wn + (lane & 7) + (lane >> 4) * 8) * ROWB + ((lane >> 3) & 1) * 16);

    float c[2][8][4];
#pragma unroll
    for (int i = 0; i < 2; i++)
#pragma unroll
        for (int j = 0; j < 8; j++)
#pragma unroll
            for (int q = 0; q < 4; q++) c[i][j][q] = 0.f;

    fetch(0);
    stage(0, 0);
    __syncthreads();

    for (int ch = 0; ch < 24; ch++) {
        int s = ch & 1;
        if (ch < 23) fetch(ch + 1);
        unsigned int ahib = sb + s * STAGEB;
        unsigned int alob = ahib + TILEB;
        unsigned int bhib = ahib + 2 * TILEB;
        unsigned int blob = ahib + 3 * TILEB;
#pragma unroll
        for (int ks = 0; ks < 2; ks++) {
            unsigned int koff = (unsigned int)(ks * 32);  // 16 halfwords = 32B
            unsigned int ah[2][4], al[2][4];
#pragma unroll
            for (int tm = 0; tm < 2; tm++) {
                unsigned int ao = a_off + tm * (16 * ROWB) + koff;
                LDSM4(ah[tm], ahib + ao);
                LDSM4(al[tm], alob + ao);
            }
#pragma unroll
            for (int tn = 0; tn < 4; tn++) {
                unsigned int bh[4], bl[4];
                unsigned int bo = b_off + tn * (16 * ROWB) + koff;
                LDSM4(bh, bhib + bo);
                LDSM4(bl, blob + bo);
#pragma unroll
                for (int tm = 0; tm < 2; tm++) {
#pragma unroll
                    for (int sub = 0; sub < 2; sub++) {
                        float* cd = c[tm][tn * 2 + sub];
                        MMA_BF16(cd, ah[tm], bh[sub * 2], bh[sub * 2 + 1]);
                        MMA_BF16(cd, ah[tm], bl[sub * 2], bl[sub * 2 + 1]);
                        MMA_BF16(cd, al[tm], bh[sub * 2], bh[sub * 2 + 1]);
                    }
                }
            }
        }
        if (ch < 23) stage(ch + 1, (ch + 1) & 1);
        __syncthreads();
    }

    // epilogue: c0,c1 -> (row, col..col+1); c2,c3 -> (row+8, ...)
#pragma unroll
    for (int tm = 0; tm < 2; tm++) {
        int r0 = rowbase + wm + tm * 16 + (lane >> 2);
#pragma unroll
        for (int tn8 = 0; tn8 < 8; tn8++) {
            int col = hbase + wn + tn8 * 8 + (lane & 3) * 2;
            float2 lo = make_float2(c[tm][tn8][0], c[tm][tn8][1]);
            float2 hi = make_float2(c[tm][tn8][2], c[tm][tn8][3]);
            *(float2*)(dst + (size_t)r0 * D_ + col) = lo;
            *(float2*)(dst + (size_t)(r0 + 8) * D_ + col) = hi;
        }
    }
}

// ---------------- slot init ------------------------------------------------
__global__ void __launch_bounds__(256) copy_slots(const float* __restrict__ prev) {
    int i = blockIdx.x * 256 + threadIdx.x;
    g_slots[i] = prev[i];
}

// ---------------- q projection (LN slots + Wq) -----------------------------
__global__ void __launch_bounds__(256) q_proj(const float* __restrict__ g_sw,
                                              const float* __restrict__ b_sw) {
    int idx = blockIdx.x;  // b*8+k
    int t = threadIdx.x;
    __shared__ float r1[256], r2[256], lnv[256];
    float x = g_slots[idx * D_ + t];
    r1[t] = x; r2[t] = x * x;
    __syncthreads();
    for (int o = 128; o; o >>= 1) {
        if (t < o) { r1[t] += r1[t + o]; r2[t] += r2[t + o]; }
        __syncthreads();
    }
    float mean = r1[0] * (1.f / 256.f);
    float var  = r2[0] * (1.f / 256.f) - mean * mean;
    float rstd = rsqrtf(var + 1e-5f);
    __syncthreads();
    lnv[t] = (x - mean) * rstd * g_sw[t] + b_sw[t];
    __syncthreads();
    float acc = 0.f;
#pragma unroll 8
    for (int d = 0; d < 256; d++) acc += lnv[d] * g_WqT[d * 256 + t];
    g_q[idx * D_ + t] = acc;
}

// ---------------- logits + softmax over K + partial row sums ---------------
__global__ void __launch_bounds__(256) logits_softmax(float* __restrict__ attn_ext,
                                                      int to_ext) {
    int b = blockIdx.x, c = blockIdx.y;
    int t = threadIdx.x, w = t >> 5, lane = t & 31;
    float* attn_out = to_ext ? attn_ext : g_attn;

    __shared__ float4 qs4[K_ * 64];  // 8 slots x 256 floats
    __shared__ float wsum[8][K_];
    const float4* qg = (const float4*)(g_q + b * K_ * D_);
    for (int i = t; i < K_ * 64; i += 256) qs4[i] = qg[i];
    __syncthreads();

    float accS[K_];
#pragma unroll
    for (int s = 0; s < K_; s++) accS[s] = 0.f;

    int nbase = c * 256;
    for (int it = 0; it < 32; it++) {
        int n = nbase + w + it * 8;
        const float4* kp = (const float4*)(g_kmat + ((size_t)(b * N_ + n)) * D_);
        float4 k0 = kp[lane], k1 = kp[32 + lane];
        float dots[K_];
#pragma unroll
        for (int s = 0; s < K_; s++) {
            float4 qa = qs4[s * 64 + lane];
            float4 qb = qs4[s * 64 + 32 + lane];
            float p = k0.x * qa.x + k0.y * qa.y + k0.z * qa.z + k0.w * qa.w +
                      k1.x * qb.x + k1.y * qb.y + k1.z * qb.z + k1.w * qb.w;
#pragma unroll
            for (int off = 16; off; off >>= 1) p += __shfl_xor_sync(0xFFFFFFFFu, p, off);
            dots[s] = p * SCALE_;
        }
        float mx = dots[0];
#pragma unroll
        for (int s = 1; s < K_; s++) mx = fmaxf(mx, dots[s]);
        float e[K_], den = 0.f;
#pragma unroll
        for (int s = 0; s < K_; s++) { e[s] = expf(dots[s] - mx); den += e[s]; }
        float inv = 1.f / den;
#pragma unroll
        for (int s = 0; s < K_; s++) accS[s] += e[s] * inv;
        if (lane < K_)
            attn_out[((size_t)(b * K_ + lane)) * N_ + n] = e[lane] * inv;
    }
    if (lane < K_) wsum[w][lane] = accS[lane];
    __syncthreads();
    if (t < K_) {
        float sm = 0.f;
        for (int w2 = 0; w2 < 8; w2++) sm += wsum[w2][t];
        g_partial[(b * K_ + t) * NCHUNK + c] = sm;
    }
}

// ---------------- deterministic row-sum reduce -----------------------------
__global__ void __launch_bounds__(256) rowsum_reduce() {
    int t = threadIdx.x;  // 256 = B*K
    float s = 0.f;
#pragma unroll
    for (int c = 0; c < NCHUNK; c++) s += g_partial[t * NCHUNK + c];
    g_rowsum[t] = s;
}

// ---------------- updates = attn_n @ v (n-split partials) ------------------
__global__ void __launch_bounds__(256) upd_partial() {
    int b = blockIdx.x, c = blockIdx.y;
    int t = threadIdx.x;
    __shared__ float an[K_][256];
#pragma unroll
    for (int s = 0; s < K_; s++) {
        float inv = 1.f / (g_rowsum[b * K_ + s] + EPS_);
        an[s][t] = g_attn[((size_t)(b * K_ + s)) * N_ + c * 256 + t] * inv;
    }
    __syncthreads();
    float acc[K_];
#pragma unroll
    for (int s = 0; s < K_; s++) acc[s] = 0.f;
    const float* vp = g_vmat + ((size_t)(b * N_ + c * 256)) * D_ + t;
#pragma unroll 4
    for (int nn = 0; nn < 256; nn++) {
        float v = vp[(size_t)nn * D_];
#pragma unroll
        for (int s = 0; s < K_; s++) acc[s] += an[s][nn] * v;
    }
    float* up = g_updpart + ((size_t)((b * NCHUNK + c) * K_)) * D_ + t;
#pragma unroll
    for (int s = 0; s < K_; s++) up[s * D_] = acc[s];
}

// ---------------- GRU cell + LN + MLP (per slot) ---------------------------
__global__ void __launch_bounds__(256) gru_mlp(const float* __restrict__ b_ih,
                                               const float* __restrict__ b_hh,
                                               const float* __restrict__ g_mw,
                                               const float* __restrict__ b_mw,
                                               const float* __restrict__ b1,
                                               const float* __restrict__ b2) {
    int idx = blockIdx.x;  // b*8+k
    int b = idx >> 3, k = idx & 7;
    int t = threadIdx.x;
    __shared__ float upd[256], slt[256], lnbuf[256], mbuf[256], r1[256], r2[256];

    float u = 0.f;
#pragma unroll
    for (int c = 0; c < NCHUNK; c++)
        u += g_updpart[((size_t)((b * NCHUNK + c) * K_ + k)) * D_ + t];
    upd[t] = u;
    float sv = g_slots[idx * D_ + t];
    slt[t] = sv;
    __syncthreads();

    float gir = b_ih[t], giz = b_ih[256 + t], gin = b_ih[512 + t];
    float ghr = b_hh[t], ghz = b_hh[256 + t], ghn = b_hh[512 + t];
#pragma unroll 4
    for (int d = 0; d < 256; d++) {
        float ud = upd[d], sd = slt[d];
        const float* wi = &g_WihT[d * 768];
        const float* wh = &g_WhhT[d * 768];
        gir += ud * wi[t];       ghr += sd * wh[t];
        giz += ud * wi[256 + t]; ghz += sd * wh[256 + t];
        gin += ud * wi[512 + t]; ghn += sd * wh[512 + t];
    }
    float r = 1.f / (1.f + expf(-(gir + ghr)));
    float z = 1.f / (1.f + expf(-(giz + ghz)));
    float nn = tanhf(gin + r * ghn);
    float h = (1.f - z) * nn + z * sv;

    r1[t] = h; r2[t] = h * h;
    __syncthreads();
    for (int o = 128; o; o >>= 1) {
        if (t < o) { r1[t] += r1[t + o]; r2[t] += r2[t + o]; }
        __syncthreads();
    }
    float mean = r1[0] * (1.f / 256.f);
    float var  = r2[0] * (1.f / 256.f) - mean * mean;
    float rstd = rsqrtf(var + 1e-5f);
    __syncthreads();
    lnbuf[t] = (h - mean) * rstd * g_mw[t] + b_mw[t];
    __syncthreads();

    float acc = b1[t];
#pragma unroll 8
    for (int d = 0; d < 256; d++) acc += lnbuf[d] * g_W1T[d * 256 + t];
    mbuf[t] = fmaxf(acc, 0.f);
    __syncthreads();

    float o = h + b2[t];
#pragma unroll 8
    for (int j = 0; j < 256; j++) o += mbuf[j] * g_W2T[j * 256 + t];
    g_slots[idx * D_ + t] = o;
}

// ---------------- final confidence blend -----------------------------------
__global__ void __launch_bounds__(256) blend(const float* __restrict__ prev,
                                             float* __restrict__ out_slots) {
    int idx = blockIdx.x;  // b*8+k
    int t = threadIdx.x;
    float mask = 1.f / (1.f + expf(-g_rowsum[idx] * (1.f / (float)N_)));
    out_slots[idx * D_ + t] =
        g_slots[idx * D_ + t] * mask + prev[idx * D_ + t] * (1.f - mask);
}

// ---------------- launch ----------------------------------------------------
extern "C" void kernel_launch(void* const* d_in, const int* in_sizes, int n_in,
                              void* d_out, int out_size) {
    const float* features = (const float*)d_in[0];
    const float* prev_slots = (const float*)d_in[1];
    const float* gin  = (const float*)d_in[2];
    const float* bin  = (const float*)d_in[3];
    const float* g_sw = (const float*)d_in[4];
    const float* b_sw = (const float*)d_in[5];
    const float* g_mw = (const float*)d_in[6];
    const float* b_mw = (const float*)d_in[7];
    const float* Wq   = (const float*)d_in[8];
    const float* Wk   = (const float*)d_in[9];
    const float* Wv   = (const float*)d_in[10];
    const float* W_ih = (const float*)d_in[11];
    const float* W_hh = (const float*)d_in[12];
    const float* b_ih = (const float*)d_in[13];
    const float* b_hh = (const float*)d_in[14];
    const float* W1   = (const float*)d_in[15];
    const float* b1   = (const float*)d_in[16];
    const float* W2   = (const float*)d_in[17];
    const float* b2   = (const float*)d_in[18];

    float* out = (float*)d_out;
    float* out_slots = out;                       // (B, K, 256)
    float* out_attn  = out + B_ * K_ * D_;        // (B, K, N)

    // opt-in to 80KB dynamic smem (host-side attribute set; not an allocation)
    cudaFuncSetAttribute(kv_mma, cudaFuncAttributeMaxDynamicSharedMemorySize, SMEM_MMA);

    ln_stats<<<NB_, 256>>>(features);
    transpose_k<<<dim3(256 / 32, 768 / 32), dim3(32, 8)>>>(W_ih, 768, 256, 0);
    transpose_k<<<dim3(256 / 32, 768 / 32), dim3(32, 8)>>>(W_hh, 768, 256, 1);
    transpose_k<<<dim3(256 / 32, 256 / 32), dim3(32, 8)>>>(W1, 256, 256, 2);
    transpose_k<<<dim3(256 / 32, 256 / 32), dim3(32, 8)>>>(W2, 256, 256, 3);
    transpose_k<<<dim3(256 / 32, 256 / 32), dim3(32, 8)>>>(Wq, 256, 256, 4);

    kv_mma<<<dim3(4, NB_ / 128), 256, SMEM_MMA>>>(features, gin, bin, Wk, Wv);
    copy_slots<<<(B_ * K_ * D_) / 256, 256>>>(prev_slots);

    for (int it = 0; it < 3; it++) {
        q_proj<<<B_ * K_, 256>>>(g_sw, b_sw);
        logits_softmax<<<dim3(B_, NCHUNK), 256>>>(out_attn, 0);
        rowsum_reduce<<<1, 256>>>();
        upd_partial<<<dim3(B_, NCHUNK), 256>>>();
        gru_mlp<<<B_ * K_, 256>>>(b_ih, b_hh, g_mw, b_mw, b1, b2);
    }

    // final attention (written straight to output) + blend
    q_proj<<<B_ * K_, 256>>>(g_sw, b_sw);
    logits_softmax<<<dim3(B_, NCHUNK), 256>>>(out_attn, 1);
    rowsum_reduce<<<1, 256>>>();
    blend<<<B_ * K_, 256>>>(prev_slots, out_slots);
}

// round 5
// speedup vs baseline: 2.2945x; 1.0906x over previous
#include <cuda_runtime.h>
#include <cuda_bf16.h>
#include <math.h>
#include <stdint.h>

// Problem constants
#define B_    32
#define N_    4096
#define F_    768
#define K_    8
#define D_    256
#define NB_   (B_ * N_)          // 131072 rows
#define NCHUNK 16                // n split into 16 chunks of 256
#define SCALE_ 0.0625f           // 256^-0.5
#define EPS_   1e-8f

// ---------------- scratch (device globals; no allocation allowed) ----------
__device__ float g_kmat[(size_t)NB_ * D_];      // (B,N,256) k
__device__ float g_vmat[(size_t)NB_ * D_];      // (B,N,256) v
__device__ float g_attn[(size_t)B_ * K_ * N_];  // iteration attn
__device__ float g_q[B_ * K_ * D_];
__device__ float g_slots[B_ * K_ * D_];
__device__ float g_partial[B_ * K_ * NCHUNK];
__device__ float g_rowsum[B_ * K_];
__device__ float g_updpart[(size_t)B_ * NCHUNK * K_ * D_];
__device__ float g_WihT[768 * 256];
__device__ float g_WhhT[768 * 256];
__device__ float g_W1T[256 * 256];
__device__ float g_W2T[256 * 256];
__device__ float g_WqT[256 * 256];
// preconverted bf16 hi/lo operands for the big GEMM
__device__ __nv_bfloat16 g_afh[(size_t)NB_ * F_];   // LN(features) hi
__device__ __nv_bfloat16 g_afl[(size_t)NB_ * F_];   // LN(features) lo
__device__ __nv_bfloat16 g_wbh[512 * F_];           // [Wk;Wv] hi
__device__ __nv_bfloat16 g_wbl[512 * F_];           // [Wk;Wv] lo

// =================== portable mma.sync helpers =============================
static __device__ __forceinline__ unsigned int smem_u32(const void* p) {
    unsigned int a;
    asm("{ .reg .u64 t; cvta.to.shared.u64 t, %1; cvt.u32.u64 %0, t; }"
        : "=r"(a) : "l"(p));
    return a;
}

#define LDSM4(R, addr)                                                         \
    asm volatile("ldmatrix.sync.aligned.m8n8.x4.shared.b16 {%0,%1,%2,%3}, [%4];" \
        : "=r"((R)[0]), "=r"((R)[1]), "=r"((R)[2]), "=r"((R)[3]) : "r"(addr))

#define MMA_BF16(D, A, B0, B1)                                                 \
    asm volatile("mma.sync.aligned.m16n8k16.row.col.f32.bf16.bf16.f32 "        \
        "{%0,%1,%2,%3},{%4,%5,%6,%7},{%8,%9},{%0,%1,%2,%3};"                   \
        : "+f"((D)[0]), "+f"((D)[1]), "+f"((D)[2]), "+f"((D)[3])               \
        : "r"((A)[0]), "r"((A)[1]), "r"((A)[2]), "r"((A)[3]), "r"(B0), "r"(B1))

#define STS128A(addr, a, b, c, d) \
    asm volatile("st.shared.v4.b32 [%0], {%1,%2,%3,%4};" :: "r"(addr), "r"(a), "r"(b), "r"(c), "r"(d) : "memory")

// SMEM layout for kv_mma (bytes): per stage Ahi/Alo/Bhi/Blo each 128 rows x 80B
#define ROWB   80      // 40 halfwords per row (32 data + 8 pad)
#define TILEB  10240   // 128 * 80
#define STAGEB (4 * TILEB)          // 40960
#define SMEM_MMA (2 * STAGEB)       // 81920

// ---------------- fused LN + bf16 hi/lo conversion of features -------------
__global__ void __launch_bounds__(256) ln_conv(const float* __restrict__ feat,
                                               const float* __restrict__ gin,
                                               const float* __restrict__ bin) {
    int row = blockIdx.x;
    const float* p = feat + (size_t)row * F_;
    int t = threadIdx.x;
    float x0 = p[t], x1 = p[t + 256], x2 = p[t + 512];
    float s  = x0 + x1 + x2;
    float ss = x0 * x0 + x1 * x1 + x2 * x2;
    __shared__ float r1[256], r2[256];
    r1[t] = s; r2[t] = ss;
    __syncthreads();
    for (int o = 128; o; o >>= 1) {
        if (t < o) { r1[t] += r1[t + o]; r2[t] += r2[t + o]; }
        __syncthreads();
    }
    float mean = r1[0] * (1.f / 768.f);
    float var  = r2[0] * (1.f / 768.f) - mean * mean;
    float rstd = rsqrtf(var + 1e-5f);

    float xs[3] = {x0, x1, x2};
    __nv_bfloat16* oh = g_afh + (size_t)row * F_;
    __nv_bfloat16* ol = g_afl + (size_t)row * F_;
#pragma unroll
    for (int j = 0; j < 3; j++) {
        int idx = t + 256 * j;
        float y = (xs[j] - mean) * rstd * gin[idx] + bin[idx];
        __nv_bfloat16 hi = __float2bfloat16_rn(y);
        __nv_bfloat16 lo = __float2bfloat16_rn(y - __bfloat162float(hi));
        oh[idx] = hi;
        ol[idx] = lo;
    }
}

// ---------------- weight bf16 hi/lo conversion -----------------------------
__global__ void __launch_bounds__(256) wconv(const float* __restrict__ Wk,
                                             const float* __restrict__ Wv) {
    int row = blockIdx.x;   // 0..511 : 0-255 -> Wk row, 256-511 -> Wv row
    int t = threadIdx.x;
    const float* src = (row < 256) ? (Wk + (size_t)row * F_) : (Wv + (size_t)(row - 256) * F_);
    __nv_bfloat16* oh = g_wbh + (size_t)row * F_;
    __nv_bfloat16* ol = g_wbl + (size_t)row * F_;
#pragma unroll
    for (int j = 0; j < 3; j++) {
        int idx = t + 256 * j;
        float x = src[idx];
        __nv_bfloat16 hi = __float2bfloat16_rn(x);
        __nv_bfloat16 lo = __float2bfloat16_rn(x - __bfloat162float(hi));
        oh[idx] = hi;
        ol[idx] = lo;
    }
}

// ---------------- generic transpose into device-global targets ------------
__device__ __forceinline__ float* tgt_ptr(int sel) {
    switch (sel) {
        case 0: return g_WihT;
        case 1: return g_WhhT;
        case 2: return g_W1T;
        case 3: return g_W2T;
        default: return g_WqT;
    }
}

__global__ void transpose_k(const float* __restrict__ src, int R, int C, int sel) {
    __shared__ float tile[32][33];
    float* dst = tgt_ptr(sel);
    int bx = blockIdx.x * 32, by = blockIdx.y * 32;
    int x = bx + threadIdx.x;
    for (int i = 0; i < 32; i += 8) {
        int y = by + threadIdx.y + i;
        if (y < R && x < C) tile[threadIdx.y + i][threadIdx.x] = src[(size_t)y * C + x];
    }
    __syncthreads();
    int x2 = by + threadIdx.x;
    for (int i = 0; i < 32; i += 8) {
        int y2 = bx + threadIdx.y + i;
        if (y2 < C && x2 < R) dst[(size_t)y2 * R + x2] = tile[threadIdx.x][threadIdx.y + i];
    }
}

// ---------------- bf16x3 HMMA K/V projection (preconverted operands) -------
// C[131072, 512] = LN(features) @ [Wk;Wv]^T via mma.sync m16n8k16 bf16 with
// hi/lo operand splitting (3 MMAs per product term), fp32 accumulation.
// CTA tile 128x128, K chunks of 32, double-buffered SMEM; stage() is pure copy.
__global__ void __launch_bounds__(256) kv_mma() {
    extern __shared__ char smem[];
    unsigned int sb = smem_u32(smem);
    int t = threadIdx.x, wid = t >> 5, lane = t & 31;
    int bx = blockIdx.x;                    // 0,1 -> k out ; 2,3 -> v out
    int rowbase = blockIdx.y * 128;
    float* __restrict__ dst = (bx < 2) ? g_kmat : g_vmat;
    int hbase = (bx & 1) * 128;             // output col base
    int wbase = ((bx < 2) ? 0 : 256) + hbase;  // row base in g_wbh/g_wbl

    // loader role: thread t -> row t>>1, 16-half segment (t&1)
    int lrow = t >> 1, lh = t & 1;
    const uint4* ah_p = (const uint4*)(g_afh + (size_t)(rowbase + lrow) * F_);
    const uint4* al_p = (const uint4*)(g_afl + (size_t)(rowbase + lrow) * F_);
    const uint4* bh_p = (const uint4*)(g_wbh + (size_t)(wbase + lrow) * F_);
    const uint4* bl_p = (const uint4*)(g_wbl + (size_t)(wbase + lrow) * F_);
    unsigned int rowoff = (unsigned int)(lrow * ROWB + lh * 32);

    uint4 rah[2], ral[2], rbh[2], rbl[2];
    auto fetch = [&](int c) {
        int q0 = (c * 32 + lh * 16) >> 3;   // uint4 index (8 halfs per uint4)
        rah[0] = ah_p[q0]; rah[1] = ah_p[q0 + 1];
        ral[0] = al_p[q0]; ral[1] = al_p[q0 + 1];
        rbh[0] = bh_p[q0]; rbh[1] = bh_p[q0 + 1];
        rbl[0] = bl_p[q0]; rbl[1] = bl_p[q0 + 1];
    };
    auto stage = [&](int s) {
        unsigned int stb = sb + s * STAGEB;
        STS128A(stb + rowoff,                  rah[0].x, rah[0].y, rah[0].z, rah[0].w);
        STS128A(stb + rowoff + 16,             rah[1].x, rah[1].y, rah[1].z, rah[1].w);
        STS128A(stb + TILEB + rowoff,          ral[0].x, ral[0].y, ral[0].z, ral[0].w);
        STS128A(stb + TILEB + rowoff + 16,     ral[1].x, ral[1].y, ral[1].z, ral[1].w);
        STS128A(stb + 2 * TILEB + rowoff,      rbh[0].x, rbh[0].y, rbh[0].z, rbh[0].w);
        STS128A(stb + 2 * TILEB + rowoff + 16, rbh[1].x, rbh[1].y, rbh[1].z, rbh[1].w);
        STS128A(stb + 3 * TILEB + rowoff,      rbl[0].x, rbl[0].y, rbl[0].z, rbl[0].w);
        STS128A(stb + 3 * TILEB + rowoff + 16, rbl[1].x, rbl[1].y, rbl[1].z, rbl[1].w);
    };

    // warp tile: 32(m) x 64(n); warp grid 4(m) x 2(n)
    int wm = (wid & 3) * 32, wn = (wid >> 2) * 64;
    unsigned int a_off = (unsigned int)((wm + (lane & 7) + ((lane >> 3) & 1) * 8) * ROWB + (lane >> 4) * 16);
    unsigned int b_off = (unsigned int)((wn + (lane & 7) + (lane >> 4) * 8) * ROWB + ((lane >> 3) & 1) * 16);

    float c[2][8][4];
#pragma unroll
    for (int i = 0; i < 2; i++)
#pragma unroll
        for (int j = 0; j < 8; j++)
#pragma unroll
            for (int q = 0; q < 4; q++) c[i][j][q] = 0.f;

    fetch(0);
    stage(0);
    __syncthreads();

    for (int ch = 0; ch < 24; ch++) {
        int s = ch & 1;
        if (ch < 23) fetch(ch + 1);
        unsigned int ahib = sb + s * STAGEB;
        unsigned int alob = ahib + TILEB;
        unsigned int bhib = ahib + 2 * TILEB;
        unsigned int blob = ahib + 3 * TILEB;
#pragma unroll
        for (int ks = 0; ks < 2; ks++) {
            unsigned int koff = (unsigned int)(ks * 32);  // 16 halfwords = 32B
            unsigned int ah[2][4], al[2][4];
#pragma unroll
            for (int tm = 0; tm < 2; tm++) {
                unsigned int ao = a_off + tm * (16 * ROWB) + koff;
                LDSM4(ah[tm], ahib + ao);
                LDSM4(al[tm], alob + ao);
            }
#pragma unroll
            for (int tn = 0; tn < 4; tn++) {
                unsigned int bh[4], bl[4];
                unsigned int bo = b_off + tn * (16 * ROWB) + koff;
                LDSM4(bh, bhib + bo);
                LDSM4(bl, blob + bo);
#pragma unroll
                for (int tm = 0; tm < 2; tm++) {
#pragma unroll
                    for (int sub = 0; sub < 2; sub++) {
                        float* cd = c[tm][tn * 2 + sub];
                        MMA_BF16(cd, ah[tm], bh[sub * 2], bh[sub * 2 + 1]);
                        MMA_BF16(cd, ah[tm], bl[sub * 2], bl[sub * 2 + 1]);
                        MMA_BF16(cd, al[tm], bh[sub * 2], bh[sub * 2 + 1]);
                    }
                }
            }
        }
        if (ch < 23) stage((ch + 1) & 1);
        __syncthreads();
    }

    // epilogue
#pragma unroll
    for (int tm = 0; tm < 2; tm++) {
        int r0 = rowbase + wm + tm * 16 + (lane >> 2);
#pragma unroll
        for (int tn8 = 0; tn8 < 8; tn8++) {
            int col = hbase + wn + tn8 * 8 + (lane & 3) * 2;
            float2 lo = make_float2(c[tm][tn8][0], c[tm][tn8][1]);
            float2 hi = make_float2(c[tm][tn8][2], c[tm][tn8][3]);
            *(float2*)(dst + (size_t)r0 * D_ + col) = lo;
            *(float2*)(dst + (size_t)(r0 + 8) * D_ + col) = hi;
        }
    }
}

// ---------------- slot init ------------------------------------------------
__global__ void __launch_bounds__(256) copy_slots(const float* __restrict__ prev) {
    int i = blockIdx.x * 256 + threadIdx.x;
    g_slots[i] = prev[i];
}

// ---------------- q projection (LN slots + Wq) -----------------------------
__global__ void __launch_bounds__(256) q_proj(const float* __restrict__ g_sw,
                                              const float* __restrict__ b_sw) {
    int idx = blockIdx.x;  // b*8+k
    int t = threadIdx.x;
    __shared__ float r1[256], r2[256], lnv[256];
    float x = g_slots[idx * D_ + t];
    r1[t] = x; r2[t] = x * x;
    __syncthreads();
    for (int o = 128; o; o >>= 1) {
        if (t < o) { r1[t] += r1[t + o]; r2[t] += r2[t + o]; }
        __syncthreads();
    }
    float mean = r1[0] * (1.f / 256.f);
    float var  = r2[0] * (1.f / 256.f) - mean * mean;
    float rstd = rsqrtf(var + 1e-5f);
    __syncthreads();
    lnv[t] = (x - mean) * rstd * g_sw[t] + b_sw[t];
    __syncthreads();
    float acc = 0.f;
#pragma unroll 8
    for (int d = 0; d < 256; d++) acc += lnv[d] * g_WqT[d * 256 + t];
    g_q[idx * D_ + t] = acc;
}

// ---------------- logits + softmax over K (one token per thread) -----------
// grid (B, 16), 256 threads. k tile staged in SMEM, q broadcast from SMEM.
__global__ void __launch_bounds__(256) logits_softmax(float* __restrict__ attn_ext,
                                                      int to_ext) {
    int b = blockIdx.x, c = blockIdx.y;
    int t = threadIdx.x, w = t >> 5, lane = t & 31;
    float* attn_out = to_ext ? attn_ext : g_attn;

    __shared__ float ks[256 * 36];    // 256 tokens x 32 d-chunk (+4 pad)
    __shared__ float qs[8 * 264];     // 8 slots x 256 d (+8 pad)
    __shared__ float wsum[8][8];

    const float* qg = g_q + b * K_ * D_;
#pragma unroll
    for (int j = 0; j < 8; j++) {
        int f = j * 256 + t;
        qs[(f >> 8) * 264 + (f & 255)] = qg[f];
    }

    float acc[K_];
#pragma unroll
    for (int s = 0; s < K_; s++) acc[s] = 0.f;

    const float4* kg = (const float4*)(g_kmat + ((size_t)(b * N_ + c * 256)) * D_);

    for (int ch = 0; ch < 8; ch++) {
        __syncthreads();
#pragma unroll
        for (int i = 0; i < 8; i++) {
            int f = i * 256 + t;          // 0..2047
            int r = f >> 3, dq = f & 7;
            float4 v = kg[(size_t)r * 64 + ch * 8 + dq];
            *(float4*)&ks[r * 36 + dq * 4] = v;
        }
        __syncthreads();
#pragma unroll
        for (int dq = 0; dq < 8; dq++) {
            float4 kv = *(float4*)&ks[t * 36 + dq * 4];
#pragma unroll
            for (int s = 0; s < K_; s++) {
                float4 qv = *(float4*)&qs[s * 264 + ch * 32 + dq * 4];
                acc[s] += kv.x * qv.x + kv.y * qv.y + kv.z * qv.z + kv.w * qv.w;
            }
        }
    }

    float mx = acc[0] * SCALE_;
#pragma unroll
    for (int s = 0; s < K_; s++) { acc[s] *= SCALE_; mx = fmaxf(mx, acc[s]); }
    float e[K_], den = 0.f;
#pragma unroll
    for (int s = 0; s < K_; s++) { e[s] = expf(acc[s] - mx); den += e[s]; }
    float inv = 1.f / den;
    int n = c * 256 + t;
#pragma unroll
    for (int s = 0; s < K_; s++) {
        e[s] *= inv;
        attn_out[((size_t)(b * K_ + s)) * N_ + n] = e[s];
    }
    // per-slot partial sums over this block's 256 tokens
#pragma unroll
    for (int s = 0; s < K_; s++) {
        float r = e[s];
#pragma unroll
        for (int off = 16; off; off >>= 1) r += __shfl_xor_sync(0xFFFFFFFFu, r, off);
        if (lane == 0) wsum[w][s] = r;
    }
    __syncthreads();
    if (t < K_) {
        float sm = 0.f;
#pragma unroll
        for (int w2 = 0; w2 < 8; w2++) sm += wsum[w2][t];
        g_partial[(b * K_ + t) * NCHUNK + c] = sm;
    }
}

// ---------------- deterministic row-sum reduce -----------------------------
__global__ void __launch_bounds__(256) rowsum_reduce() {
    int t = threadIdx.x;  // 256 = B*K
    float s = 0.f;
#pragma unroll
    for (int c = 0; c < NCHUNK; c++) s += g_partial[t * NCHUNK + c];
    g_rowsum[t] = s;
}

// ---------------- updates = attn_n @ v (n-split partials) ------------------
__global__ void __launch_bounds__(256) upd_partial() {
    int b = blockIdx.x, c = blockIdx.y;
    int t = threadIdx.x;
    __shared__ float an[K_][256];
#pragma unroll
    for (int s = 0; s < K_; s++) {
        float inv = 1.f / (g_rowsum[b * K_ + s] + EPS_);
        an[s][t] = g_attn[((size_t)(b * K_ + s)) * N_ + c * 256 + t] * inv;
    }
    __syncthreads();
    float acc[K_];
#pragma unroll
    for (int s = 0; s < K_; s++) acc[s] = 0.f;
    const float* vp = g_vmat + ((size_t)(b * N_ + c * 256)) * D_ + t;
#pragma unroll 4
    for (int nn = 0; nn < 256; nn++) {
        float v = vp[(size_t)nn * D_];
#pragma unroll
        for (int s = 0; s < K_; s++) acc[s] += an[s][nn] * v;
    }
    float* up = g_updpart + ((size_t)((b * NCHUNK + c) * K_)) * D_ + t;
#pragma unroll
    for (int s = 0; s < K_; s++) up[s * D_] = acc[s];
}

// ---------------- GRU cell + LN + MLP (per slot) ---------------------------
__global__ void __launch_bounds__(256) gru_mlp(const float* __restrict__ b_ih,
                                               const float* __restrict__ b_hh,
                                               const float* __restrict__ g_mw,
                                               const float* __restrict__ b_mw,
                                               const float* __restrict__ b1,
                                               const float* __restrict__ b2) {
    int idx = blockIdx.x;  // b*8+k
    int b = idx >> 3, k = idx & 7;
    int t = threadIdx.x;
    __shared__ float upd[256], slt[256], lnbuf[256], mbuf[256], r1[256], r2[256];

    float u = 0.f;
#pragma unroll
    for (int c = 0; c < NCHUNK; c++)
        u += g_updpart[((size_t)((b * NCHUNK + c) * K_ + k)) * D_ + t];
    upd[t] = u;
    float sv = g_slots[idx * D_ + t];
    slt[t] = sv;
    __syncthreads();

    float gir = b_ih[t], giz = b_ih[256 + t], gin = b_ih[512 + t];
    float ghr = b_hh[t], ghz = b_hh[256 + t], ghn = b_hh[512 + t];
#pragma unroll 4
    for (int d = 0; d < 256; d++) {
        float ud = upd[d], sd = slt[d];
        const float* wi = &g_WihT[d * 768];
        const float* wh = &g_WhhT[d * 768];
        gir += ud * wi[t];       ghr += sd * wh[t];
        giz += ud * wi[256 + t]; ghz += sd * wh[256 + t];
        gin += ud * wi[512 + t]; ghn += sd * wh[512 + t];
    }
    float r = 1.f / (1.f + expf(-(gir + ghr)));
    float z = 1.f / (1.f + expf(-(giz + ghz)));
    float nn = tanhf(gin + r * ghn);
    float h = (1.f - z) * nn + z * sv;

    r1[t] = h; r2[t] = h * h;
    __syncthreads();
    for (int o = 128; o; o >>= 1) {
        if (t < o) { r1[t] += r1[t + o]; r2[t] += r2[t + o]; }
        __syncthreads();
    }
    float mean = r1[0] * (1.f / 256.f);
    float var  = r2[0] * (1.f / 256.f) - mean * mean;
    float rstd = rsqrtf(var + 1e-5f);
    __syncthreads();
    lnbuf[t] = (h - mean) * rstd * g_mw[t] + b_mw[t];
    __syncthreads();

    float acc = b1[t];
#pragma unroll 8
    for (int d = 0; d < 256; d++) acc += lnbuf[d] * g_W1T[d * 256 + t];
    mbuf[t] = fmaxf(acc, 0.f);
    __syncthreads();

    float o = h + b2[t];
#pragma unroll 8
    for (int j = 0; j < 256; j++) o += mbuf[j] * g_W2T[j * 256 + t];
    g_slots[idx * D_ + t] = o;
}

// ---------------- final confidence blend -----------------------------------
__global__ void __launch_bounds__(256) blend(const float* __restrict__ prev,
                                             float* __restrict__ out_slots) {
    int idx = blockIdx.x;  // b*8+k
    int t = threadIdx.x;
    float mask = 1.f / (1.f + expf(-g_rowsum[idx] * (1.f / (float)N_)));
    out_slots[idx * D_ + t] =
        g_slots[idx * D_ + t] * mask + prev[idx * D_ + t] * (1.f - mask);
}

// ---------------- launch ----------------------------------------------------
extern "C" void kernel_launch(void* const* d_in, const int* in_sizes, int n_in,
                              void* d_out, int out_size) {
    const float* features = (const float*)d_in[0];
    const float* prev_slots = (const float*)d_in[1];
    const float* gin  = (const float*)d_in[2];
    const float* bin  = (const float*)d_in[3];
    const float* g_sw = (const float*)d_in[4];
    const float* b_sw = (const float*)d_in[5];
    const float* g_mw = (const float*)d_in[6];
    const float* b_mw = (const float*)d_in[7];
    const float* Wq   = (const float*)d_in[8];
    const float* Wk   = (const float*)d_in[9];
    const float* Wv   = (const float*)d_in[10];
    const float* W_ih = (const float*)d_in[11];
    const float* W_hh = (const float*)d_in[12];
    const float* b_ih = (const float*)d_in[13];
    const float* b_hh = (const float*)d_in[14];
    const float* W1   = (const float*)d_in[15];
    const float* b1   = (const float*)d_in[16];
    const float* W2   = (const float*)d_in[17];
    const float* b2   = (const float*)d_in[18];

    float* out = (float*)d_out;
    float* out_slots = out;                       // (B, K, 256)
    float* out_attn  = out + B_ * K_ * D_;        // (B, K, N)

    // opt-in to 80KB dynamic smem (host-side attribute set; not an allocation)
    cudaFuncSetAttribute(kv_mma, cudaFuncAttributeMaxDynamicSharedMemorySize, SMEM_MMA);

    ln_conv<<<NB_, 256>>>(features, gin, bin);
    wconv<<<512, 256>>>(Wk, Wv);
    transpose_k<<<dim3(256 / 32, 768 / 32), dim3(32, 8)>>>(W_ih, 768, 256, 0);
    transpose_k<<<dim3(256 / 32, 768 / 32), dim3(32, 8)>>>(W_hh, 768, 256, 1);
    transpose_k<<<dim3(256 / 32, 256 / 32), dim3(32, 8)>>>(W1, 256, 256, 2);
    transpose_k<<<dim3(256 / 32, 256 / 32), dim3(32, 8)>>>(W2, 256, 256, 3);
    transpose_k<<<dim3(256 / 32, 256 / 32), dim3(32, 8)>>>(Wq, 256, 256, 4);

    kv_mma<<<dim3(4, NB_ / 128), 256, SMEM_MMA>>>();
    copy_slots<<<(B_ * K_ * D_) / 256, 256>>>(prev_slots);

    for (int it = 0; it < 3; it++) {
        q_proj<<<B_ * K_, 256>>>(g_sw, b_sw);
        logits_softmax<<<dim3(B_, NCHUNK), 256>>>(out_attn, 0);
        rowsum_reduce<<<1, 256>>>();
        upd_partial<<<dim3(B_, NCHUNK), 256>>>();
        gru_mlp<<<B_ * K_, 256>>>(b_ih, b_hh, g_mw, b_mw, b1, b2);
    }

    // final attention (written straight to output) + blend
    q_proj<<<B_ * K_, 256>>>(g_sw, b_sw);
    logits_softmax<<<dim3(B_, NCHUNK), 256>>>(out_attn, 1);
    rowsum_reduce<<<1, 256>>>();
    blend<<<B_ * K_, 256>>>(prev_slots, out_slots);
}